// round 14
// baseline (speedup 1.0000x reference)
#include <cuda_runtime.h>
#include <cuda_bf16.h>
#include <cuda_fp16.h>
#include <cstdint>

// Problem constants
#define BB   8
#define CIN  64
#define HH   64
#define WW   64
#define OCH_OFF 1152
#define OCH_TOT 1728
#define OCP     1792          // padded oc (14 * 128)
#define OC_FIN  128
#define MAXOFF  16.0f
#define PADW 100              // padded plane 100x100, border 17

// Scratch
__device__ float g_om[(size_t)BB * OCH_TOT * HH * WW];   // conv out [b][r][y][x]
__device__ float g_wt[576 * 128];                        // w_conv transposed [ck][oc]
// paired padded x: g_xp2[b][c][yy][xx] = (xpad[yy][xx], xpad[yy][xx+1])
__device__ float2 g_xp2[(size_t)BB * CIN * PADW * PADW];
// shifted x, fp16: g_xth[kj][b][yy 0..65][cc 0..3][px 0..63][cic 0..15]
__device__ __half g_xth[3 * 8 * 66 * 4 * 64 * 16];
// conv weights fp16 split: g_wh[t][cc][ocp][cic] (zeros oc>=1728)
__device__ __half g_wh_hi[9 * 4 * OCP * 16];
__device__ __half g_wh_lo[9 * 4 * OCP * 16];

// ======================= helpers =======================
__device__ __forceinline__ uint32_t smem_u32(const void* p) {
    uint32_t a;
    asm("{ .reg .u64 t; cvta.to.shared.u64 t, %1; cvt.u32.u64 %0, t; }"
        : "=r"(a) : "l"(p));
    return a;
}
__device__ __forceinline__ void ldm_x4(uint32_t* r, uint32_t addr) {
    asm volatile("ldmatrix.sync.aligned.m8n8.x4.shared.b16 {%0,%1,%2,%3}, [%4];"
                 : "=r"(r[0]), "=r"(r[1]), "=r"(r[2]), "=r"(r[3]) : "r"(addr));
}
__device__ __forceinline__ void mma_f16(float* d, const uint32_t* a,
                                        uint32_t b0, uint32_t b1) {
    asm volatile(
        "mma.sync.aligned.m16n8k16.row.col.f32.f16.f16.f32 "
        "{%0,%1,%2,%3}, {%4,%5,%6,%7}, {%8,%9}, {%0,%1,%2,%3};"
        : "+f"(d[0]), "+f"(d[1]), "+f"(d[2]), "+f"(d[3])
        : "r"(a[0]), "r"(a[1]), "r"(a[2]), "r"(a[3]), "r"(b0), "r"(b1));
}

// ---------------- packed f32x2 helpers (deform kernel) ----------------
__device__ __forceinline__ unsigned long long ffma2(unsigned long long a,
                                                    unsigned long long b,
                                                    unsigned long long c) {
    unsigned long long d;
    asm("fma.rn.f32x2 %0, %1, %2, %3;" : "=l"(d) : "l"(a), "l"(b), "l"(c));
    return d;
}
__device__ __forceinline__ unsigned long long pack2(float lo, float hi) {
    unsigned long long d;
    asm("mov.b64 %0, {%1, %2};" : "=l"(d) : "f"(lo), "f"(hi));
    return d;
}
__device__ __forceinline__ void unpack2(unsigned long long v, float& lo, float& hi) {
    asm("mov.b64 {%0, %1}, %2;" : "=f"(lo), "=f"(hi) : "l"(v));
}

// ======================= Prep kernels =======================
__global__ void prep_xth(const float* __restrict__ x) {
    int i = blockIdx.x * 256 + threadIdx.x;
    const int TOT = 3 * 8 * 66 * 4 * 64 * 16;
    if (i >= TOT) return;
    int cic = i & 15;
    int t1 = i >> 4;
    int px = t1 & 63;
    int t2 = t1 >> 6;
    int cc = t2 & 3;
    int t3 = t2 >> 2;
    int yy = t3 % 66;
    int t4 = t3 / 66;
    int b  = t4 & 7;
    int kj = t4 >> 3;
    int c = cc * 16 + cic;
    int sy = yy - 1, sx = px + kj - 1;
    float v = 0.f;
    if (sy >= 0 && sy < HH && sx >= 0 && sx < WW)
        v = x[(((size_t)b * CIN + c) * HH + sy) * WW + sx];
    g_xth[i] = __float2half(v);
}

__global__ void prep_wh(const float* __restrict__ w_off, const float* __restrict__ w_mod) {
    int i = blockIdx.x * 256 + threadIdx.x;
    const int TOT = 9 * 4 * OCP * 16;
    if (i >= TOT) return;
    int cic = i & 15;
    int t1 = i >> 4;
    int oc = t1 % OCP;
    int tcc = t1 / OCP;
    int cc = tcc & 3;
    int tp = tcc >> 2;
    int c = cc * 16 + cic;
    float v = 0.f;
    if (oc < OCH_OFF)      v = w_off[((size_t)oc * CIN + c) * 9 + tp];
    else if (oc < OCH_TOT) v = w_mod[((size_t)(oc - OCH_OFF) * CIN + c) * 9 + tp];
    __half h = __float2half(v);
    g_wh_hi[i] = h;
    g_wh_lo[i] = __float2half(v - __half2float(h));
}

// paired padded plane: each element holds (x[yy][xx], x[yy][xx+1])
__global__ void prep_xp2(const float* __restrict__ x) {
    int i = blockIdx.x * 256 + threadIdx.x;
    const int TOT = BB * CIN * PADW * PADW;
    if (i >= TOT) return;
    int xx = i % PADW;
    int t1 = i / PADW;
    int yy = t1 % PADW;
    int bc = t1 / PADW;
    int sy = yy - 17;
    float v0 = 0.f, v1 = 0.f;
    if (sy >= 0 && sy < HH) {
        int sx0 = xx - 17, sx1 = xx - 16;
        const float* row = x + ((size_t)bc * HH + sy) * WW;
        if (sx0 >= 0 && sx0 < WW) v0 = row[sx0];
        if (sx1 >= 0 && sx1 < WW) v1 = row[sx1];
    }
    g_xp2[i] = make_float2(v0, v1);
}

__global__ void transpose_wconv(const float* __restrict__ w_conv) {
    int i = blockIdx.x * 256 + threadIdx.x;
    if (i < OC_FIN * 576) {
        int oc = i / 576, ck = i % 576;
        g_wt[ck * 128 + oc] = w_conv[i];
    }
}

// ======================= Conv kernel: fp16 split, mask CTAs 1-MMA =========
// CTA: 128 oc x 128 px (2 image rows of one b). 8 warps: wm = w&3 (oc quad),
// wn = w>>2 (row). Warp tile 32 oc x 64 px. K = 9 taps x 4 chunks of 16.
// Offset CTAs (ocBase < 1152): 2-MMA split (Wh + Wl).
// Mask CTAs (ocBase >= 1152): single Wh MMA (mask tolerates fp16 w rounding).
// SMEM double buffer of {A_hi[128][48] ; A_lo[128][48] ; B[128][48]} = 36 KB.
#define SROW 48
#define ASZ 6144               // 128*48
#define BUFSZ 18432            // A_hi + A_lo + B
__global__ __launch_bounds__(256) void conv_mma_kernel(
    const float* __restrict__ b_off, const float* __restrict__ b_mod)
{
    __shared__ __align__(16) char smem[2 * BUFSZ];   // 36 KB
    const uint32_t sb = smem_u32(smem);
    const int tid = threadIdx.x;
    const int lane = tid & 31;
    const int w = tid >> 5;
    const int wm = w & 3;
    const int wn = w >> 2;
    const int ocBase = blockIdx.x * 128;
    const int y0 = blockIdx.y * 2;
    const int b  = blockIdx.z;
    const bool needLo = (ocBase < OCH_OFF);   // block-uniform

    float d[2][8][4];
#pragma unroll
    for (int mt = 0; mt < 2; mt++)
#pragma unroll
        for (int nt = 0; nt < 8; nt++)
#pragma unroll
            for (int e = 0; e < 4; e++) d[mt][nt][e] = 0.f;

    auto stage = [&](int s, int buf) {
        const int t = s >> 2, cc = s & 3;
        const int ki = t / 3, kj = t - ki * 3;
        char* base = smem + buf * BUFSZ;
#pragma unroll
        for (int ii = 0; ii < 3; ii++) {
            int i = tid + ii * 256;
            if (i < 512) {
                int hh = i >> 8, oc = (i >> 1) & 127, j = i & 1;
                if (hh == 0 || needLo) {
                    const __half* src = (hh ? g_wh_lo : g_wh_hi)
                        + (((size_t)(t * 4 + cc) * OCP + ocBase + oc) << 4) + j * 8;
                    *(uint4*)(base + hh * ASZ + oc * SROW + j * 16) = *(const uint4*)src;
                }
            } else {
                i -= 512;
                int px = (i >> 1) & 127, j = i & 1;
                int yy = y0 + (px >> 6) + ki;
                const __half* src = g_xth
                    + ((size_t)(((kj * 8 + b) * 66 + yy) * 4 + cc) << 10)
                    + ((px & 63) << 4) + j * 8;
                *(uint4*)(base + 2 * ASZ + px * SROW + j * 16) = *(const uint4*)src;
            }
        }
    };

    stage(0, 0);
    __syncthreads();

    const int arowL = (lane & 7) + ((lane >> 3) & 1) * 8;
    const int acolB = ((lane >> 4) & 1) * 16;

    for (int s = 0; s < 36; s++) {
        const int buf = s & 1;
        if (s + 1 < 36) stage(s + 1, 1 - buf);

        const uint32_t sA = sb + buf * BUFSZ;
        const uint32_t sB = sA + 2 * ASZ;

        uint32_t a[2][2][4];
#pragma unroll
        for (int mt = 0; mt < 2; mt++) {
            ldm_x4(a[mt][0], sA + (wm * 32 + mt * 16 + arowL) * SROW + acolB);
            if (needLo)
                ldm_x4(a[mt][1], sA + ASZ + (wm * 32 + mt * 16 + arowL) * SROW + acolB);
        }

#pragma unroll
        for (int p = 0; p < 4; p++) {
            uint32_t bh[4];
            ldm_x4(bh, sB + (wn * 64 + p * 16 + arowL) * SROW + acolB);
#pragma unroll
            for (int mt = 0; mt < 2; mt++) {
#pragma unroll
                for (int q = 0; q < 2; q++) {
                    float* dd = d[mt][p * 2 + q];
                    mma_f16(dd, a[mt][0], bh[q], bh[q + 2]);       // Wh * X
                    if (needLo)
                        mma_f16(dd, a[mt][1], bh[q], bh[q + 2]);   // Wl * X
                }
            }
        }
        __syncthreads();
    }

    const int ocW = ocBase + wm * 32;
    if (ocW >= OCH_TOT) return;
    const int y = y0 + wn;
#pragma unroll
    for (int mt = 0; mt < 2; mt++) {
        int r0 = ocW + mt * 16 + (lane >> 2);
        int r1 = r0 + 8;
        float bias0 = (r0 < OCH_OFF) ? __ldg(&b_off[r0]) : __ldg(&b_mod[r0 - OCH_OFF]);
        float bias1 = (r1 < OCH_OFF) ? __ldg(&b_off[r1]) : __ldg(&b_mod[r1 - OCH_OFF]);
        bool c0 = r0 < OCH_OFF, c1 = r1 < OCH_OFF;
        float* base0 = &g_om[(((size_t)b * OCH_TOT + r0) * HH + y) * WW];
        float* base1 = &g_om[(((size_t)b * OCH_TOT + r1) * HH + y) * WW];
#pragma unroll
        for (int nt = 0; nt < 8; nt++) {
            int col = nt * 8 + (lane & 3) * 2;
            float2 v0, v1;
            v0.x = d[mt][nt][0] + bias0; v0.y = d[mt][nt][1] + bias0;
            v1.x = d[mt][nt][2] + bias1; v1.y = d[mt][nt][3] + bias1;
            if (c0) {
                v0.x = fminf(fmaxf(v0.x, -MAXOFF), MAXOFF);
                v0.y = fminf(fmaxf(v0.y, -MAXOFF), MAXOFF);
            }
            if (c1) {
                v1.x = fminf(fmaxf(v1.x, -MAXOFF), MAXOFF);
                v1.y = fminf(fmaxf(v1.y, -MAXOFF), MAXOFF);
            }
            *(float2*)(base0 + col) = v0;
            *(float2*)(base1 + col) = v1;
        }
    }
}

// ======================= Deform + final GEMM (FFMA2, paired gather) =======
// CTA = one (b, y) row: 64 px x 128 oc. 256 threads; channel chunks of 4.
// Bilinear corners come from g_xp2: 2 x LDG.64 instead of 4 x LDG.32.
__global__ __launch_bounds__(256) void deform_gemm_kernel(float* __restrict__ out)
{
    const int y = blockIdx.x;
    const int b = blockIdx.y;
    const int tid = threadIdx.x;
    const int tx = tid & 15;
    const int ty = tid >> 4;
    const int px0 = tx * 4;
    const int oc0 = ty * 8;

    __shared__ __align__(16) float ss[4 * 9 * 64];
    __shared__ __align__(16) float wcs[36][128];

    unsigned long long acc2[4][4];
#pragma unroll
    for (int p = 0; p < 4; p++)
#pragma unroll
        for (int j = 0; j < 4; j++) acc2[p][j] = 0ull;

    const float2* xpb = g_xp2 + (size_t)b * CIN * (PADW * PADW);
    const float* omb = g_om + (size_t)b * OCH_TOT * (HH * WW);

    for (int c0 = 0; c0 < CIN; c0 += 4) {
        for (int idx = tid; idx < 36 * 128; idx += 256) {
            ((float*)wcs)[idx] = g_wt[(c0 * 9 + (idx >> 7)) * 128 + (idx & 127)];
        }
        for (int s = tid; s < 4 * 9 * 64; s += 256) {
            int px = s & 63;
            int k  = (s >> 6) % 9;
            int cc = s / 576;
            int c  = c0 + cc;
            int ki = k / 3, kj = k % 3;
            float dy = __ldg(omb + (size_t)(c * 18 + 2 * k) * 4096 + y * WW + px);
            float dx = __ldg(omb + (size_t)(c * 18 + 2 * k + 1) * 4096 + y * WW + px);
            float m  = __ldg(omb + (size_t)(OCH_OFF + c * 9 + k) * 4096 + y * WW + px);
            // padded-plane coords (always in [0, 97])
            float py  = dy + (float)(y + ki + 16);
            float pxf = dx + (float)(px + kj + 16);
            int iy = (int)py, ix = (int)pxf;
            float wy = py - (float)iy, wx = pxf - (float)ix;
            const float2* p = xpb + (size_t)c * (PADW * PADW) + iy * PADW + ix;
            float2 top = __ldg(p);
            float2 bot = __ldg(p + PADW);
            float t0 = top.x + wx * (top.y - top.x);
            float t1 = bot.x + wx * (bot.y - bot.x);
            ss[s] = (t0 + wy * (t1 - t0)) * m;
        }
        __syncthreads();

#pragma unroll
        for (int ck = 0; ck < 36; ck++) {
            float4 sv4 = *(const float4*)&ss[ck * 64 + px0];
            unsigned long long sp[4];
            sp[0] = pack2(sv4.x, sv4.x);
            sp[1] = pack2(sv4.y, sv4.y);
            sp[2] = pack2(sv4.z, sv4.z);
            sp[3] = pack2(sv4.w, sv4.w);
            ulonglong2 w0 = *(const ulonglong2*)&wcs[ck][oc0];
            ulonglong2 w1 = *(const ulonglong2*)&wcs[ck][oc0 + 4];
#pragma unroll
            for (int j = 0; j < 4; j++) {
                acc2[0][j] = ffma2(w0.x, sp[j], acc2[0][j]);
                acc2[1][j] = ffma2(w0.y, sp[j], acc2[1][j]);
                acc2[2][j] = ffma2(w1.x, sp[j], acc2[2][j]);
                acc2[3][j] = ffma2(w1.y, sp[j], acc2[3][j]);
            }
        }
        __syncthreads();
    }

#pragma unroll
    for (int p = 0; p < 4; p++) {
        float lo[4], hi[4];
#pragma unroll
        for (int j = 0; j < 4; j++) unpack2(acc2[p][j], lo[j], hi[j]);
        float4 vlo = make_float4(lo[0], lo[1], lo[2], lo[3]);
        float4 vhi = make_float4(hi[0], hi[1], hi[2], hi[3]);
        int oc = oc0 + 2 * p;
        *(float4*)&out[(((size_t)b * OC_FIN + oc) * HH + y) * WW + px0] = vlo;
        *(float4*)&out[(((size_t)b * OC_FIN + oc + 1) * HH + y) * WW + px0] = vhi;
    }
}

// ---------------------------------------------------------------------------
extern "C" void kernel_launch(void* const* d_in, const int* in_sizes, int n_in,
                              void* d_out, int out_size)
{
    const float* x      = (const float*)d_in[0];
    const float* w_off  = (const float*)d_in[1];
    const float* b_off  = (const float*)d_in[2];
    const float* w_mod  = (const float*)d_in[3];
    const float* b_mod  = (const float*)d_in[4];
    const float* w_conv = (const float*)d_in[5];
    float* out = (float*)d_out;

    prep_xth<<<(3 * 8 * 66 * 4 * 64 * 16 + 255) / 256, 256>>>(x);
    prep_wh<<<(9 * 4 * OCP * 16 + 255) / 256, 256>>>(w_off, w_mod);
    prep_xp2<<<(BB * CIN * PADW * PADW + 255) / 256, 256>>>(x);
    transpose_wconv<<<(OC_FIN * 576 + 255) / 256, 256>>>(w_conv);
    conv_mma_kernel<<<dim3(14, 32, 8), 256>>>(b_off, b_mod);
    deform_gemm_kernel<<<dim3(HH, BB), 256>>>(out);
}

// round 16
// speedup vs baseline: 1.0276x; 1.0276x over previous
#include <cuda_runtime.h>
#include <cuda_bf16.h>
#include <cuda_fp16.h>
#include <cstdint>

// Problem constants
#define BB   8
#define CIN  64
#define HH   64
#define WW   64
#define OCH_OFF 1152
#define OCH_TOT 1728
#define OCP     1792          // padded oc (14 * 128)
#define OC_FIN  128
#define MAXOFF  16.0f
#define PADW 100              // padded plane 100x100, border 17

// Scratch
__device__ float g_om[(size_t)BB * OCH_TOT * HH * WW];   // conv out [b][r][y][x]
__device__ float g_wt[576 * 128];                        // w_conv transposed [ck][oc]
// zero-padded x: [b][c][100][100], (yy,xx) = (y+17, x+17)
__device__ float g_xpad[(size_t)BB * CIN * PADW * PADW];
// shifted x, fp16: g_xth[kj][b][yy 0..65][cc 0..3][px 0..63][cic 0..15]
__device__ __half g_xth[3 * 8 * 66 * 4 * 64 * 16];
// conv weights fp16 split: g_wh[t][cc][ocp][cic] (zeros oc>=1728)
__device__ __half g_wh_hi[9 * 4 * OCP * 16];
__device__ __half g_wh_lo[9 * 4 * OCP * 16];

// ======================= helpers =======================
__device__ __forceinline__ uint32_t smem_u32(const void* p) {
    uint32_t a;
    asm("{ .reg .u64 t; cvta.to.shared.u64 t, %1; cvt.u32.u64 %0, t; }"
        : "=r"(a) : "l"(p));
    return a;
}
__device__ __forceinline__ void ldm_x4(uint32_t* r, uint32_t addr) {
    asm volatile("ldmatrix.sync.aligned.m8n8.x4.shared.b16 {%0,%1,%2,%3}, [%4];"
                 : "=r"(r[0]), "=r"(r[1]), "=r"(r[2]), "=r"(r[3]) : "r"(addr));
}
__device__ __forceinline__ void mma_f16(float* d, const uint32_t* a,
                                        uint32_t b0, uint32_t b1) {
    asm volatile(
        "mma.sync.aligned.m16n8k16.row.col.f32.f16.f16.f32 "
        "{%0,%1,%2,%3}, {%4,%5,%6,%7}, {%8,%9}, {%0,%1,%2,%3};"
        : "+f"(d[0]), "+f"(d[1]), "+f"(d[2]), "+f"(d[3])
        : "r"(a[0]), "r"(a[1]), "r"(a[2]), "r"(a[3]), "r"(b0), "r"(b1));
}

// ---------------- packed f32x2 helpers (deform kernel) ----------------
__device__ __forceinline__ unsigned long long ffma2(unsigned long long a,
                                                    unsigned long long b,
                                                    unsigned long long c) {
    unsigned long long d;
    asm("fma.rn.f32x2 %0, %1, %2, %3;" : "=l"(d) : "l"(a), "l"(b), "l"(c));
    return d;
}
__device__ __forceinline__ unsigned long long pack2(float lo, float hi) {
    unsigned long long d;
    asm("mov.b64 %0, {%1, %2};" : "=l"(d) : "f"(lo), "f"(hi));
    return d;
}
__device__ __forceinline__ void unpack2(unsigned long long v, float& lo, float& hi) {
    asm("mov.b64 {%0, %1}, %2;" : "=f"(lo), "=f"(hi) : "l"(v));
}

// ======================= Merged prep kernel =======================
// Index ranges (grid must cover the LARGEST = TOT_XTH):
//   TOT_XTH  = 6,488,064   (3*8*66*4*64*16)  <-- largest
//   TOT_XPAD = 5,120,000   (BB*CIN*PADW*PADW)
//   TOT_WH   = 1,032,192   (9*4*OCP*16)
//   TOT_WT   =    73,728   (OC_FIN*576)
#define TOT_XTH  (3 * 8 * 66 * 4 * 64 * 16)
#define TOT_WH   (9 * 4 * OCP * 16)
#define TOT_XPAD (BB * CIN * PADW * PADW)
#define TOT_WT   (OC_FIN * 576)
__global__ void prep_all(const float* __restrict__ x,
                         const float* __restrict__ w_off,
                         const float* __restrict__ w_mod,
                         const float* __restrict__ w_conv) {
    int i = blockIdx.x * 256 + threadIdx.x;

    if (i < TOT_XPAD) {
        int xx = i % PADW;
        int t1 = i / PADW;
        int yy = t1 % PADW;
        int bc = t1 / PADW;
        int sy = yy - 17, sx = xx - 17;
        float v = 0.f;
        if (sy >= 0 && sy < HH && sx >= 0 && sx < WW)
            v = x[((size_t)bc * HH + sy) * WW + sx];
        g_xpad[i] = v;
    }
    if (i < TOT_XTH) {
        int cic = i & 15;
        int t1 = i >> 4;
        int px = t1 & 63;
        int t2 = t1 >> 6;
        int cc = t2 & 3;
        int t3 = t2 >> 2;
        int yy = t3 % 66;
        int t4 = t3 / 66;
        int b  = t4 & 7;
        int kj = t4 >> 3;
        int c = cc * 16 + cic;
        int sy = yy - 1, sx = px + kj - 1;
        float v = 0.f;
        if (sy >= 0 && sy < HH && sx >= 0 && sx < WW)
            v = x[(((size_t)b * CIN + c) * HH + sy) * WW + sx];
        g_xth[i] = __float2half(v);
    }
    if (i < TOT_WH) {
        int cic = i & 15;
        int t1 = i >> 4;
        int oc = t1 % OCP;
        int tcc = t1 / OCP;
        int cc = tcc & 3;
        int tp = tcc >> 2;
        int c = cc * 16 + cic;
        float v = 0.f;
        if (oc < OCH_OFF)      v = w_off[((size_t)oc * CIN + c) * 9 + tp];
        else if (oc < OCH_TOT) v = w_mod[((size_t)(oc - OCH_OFF) * CIN + c) * 9 + tp];
        __half h = __float2half(v);
        g_wh_hi[i] = h;
        g_wh_lo[i] = __float2half(v - __half2float(h));
    }
    if (i < TOT_WT) {
        int oc = i / 576, ck = i % 576;
        g_wt[ck * 128 + oc] = w_conv[i];
    }
}

// ======================= Conv kernel: fp16 split, mask CTAs 1-MMA =========
// CTA: 128 oc x 128 px (2 image rows of one b). 8 warps: wm = w&3 (oc quad),
// wn = w>>2 (row). Warp tile 32 oc x 64 px. K = 9 taps x 4 chunks of 16.
// Offset CTAs (ocBase < 1152): 2-MMA split (Wh + Wl).
// Mask CTAs (ocBase >= 1152): single Wh MMA (mask tolerates fp16 w rounding).
// g_om stores use __stcs (streaming, evict-first) to preserve L2 for g_xpad.
#define SROW 48
#define ASZ 6144               // 128*48
#define BUFSZ 18432            // A_hi + A_lo + B
__global__ __launch_bounds__(256) void conv_mma_kernel(
    const float* __restrict__ b_off, const float* __restrict__ b_mod)
{
    __shared__ __align__(16) char smem[2 * BUFSZ];   // 36 KB
    const uint32_t sb = smem_u32(smem);
    const int tid = threadIdx.x;
    const int lane = tid & 31;
    const int w = tid >> 5;
    const int wm = w & 3;
    const int wn = w >> 2;
    const int ocBase = blockIdx.x * 128;
    const int y0 = blockIdx.y * 2;
    const int b  = blockIdx.z;
    const bool needLo = (ocBase < OCH_OFF);   // block-uniform

    float d[2][8][4];
#pragma unroll
    for (int mt = 0; mt < 2; mt++)
#pragma unroll
        for (int nt = 0; nt < 8; nt++)
#pragma unroll
            for (int e = 0; e < 4; e++) d[mt][nt][e] = 0.f;

    auto stage = [&](int s, int buf) {
        const int t = s >> 2, cc = s & 3;
        const int ki = t / 3, kj = t - ki * 3;
        char* base = smem + buf * BUFSZ;
#pragma unroll
        for (int ii = 0; ii < 3; ii++) {
            int i = tid + ii * 256;
            if (i < 512) {
                int hh = i >> 8, oc = (i >> 1) & 127, j = i & 1;
                if (hh == 0 || needLo) {
                    const __half* src = (hh ? g_wh_lo : g_wh_hi)
                        + (((size_t)(t * 4 + cc) * OCP + ocBase + oc) << 4) + j * 8;
                    *(uint4*)(base + hh * ASZ + oc * SROW + j * 16) = *(const uint4*)src;
                }
            } else {
                i -= 512;
                int px = (i >> 1) & 127, j = i & 1;
                int yy = y0 + (px >> 6) + ki;
                const __half* src = g_xth
                    + ((size_t)(((kj * 8 + b) * 66 + yy) * 4 + cc) << 10)
                    + ((px & 63) << 4) + j * 8;
                *(uint4*)(base + 2 * ASZ + px * SROW + j * 16) = *(const uint4*)src;
            }
        }
    };

    stage(0, 0);
    __syncthreads();

    const int arowL = (lane & 7) + ((lane >> 3) & 1) * 8;
    const int acolB = ((lane >> 4) & 1) * 16;

    for (int s = 0; s < 36; s++) {
        const int buf = s & 1;
        if (s + 1 < 36) stage(s + 1, 1 - buf);

        const uint32_t sA = sb + buf * BUFSZ;
        const uint32_t sB = sA + 2 * ASZ;

        uint32_t a[2][2][4];
#pragma unroll
        for (int mt = 0; mt < 2; mt++) {
            ldm_x4(a[mt][0], sA + (wm * 32 + mt * 16 + arowL) * SROW + acolB);
            if (needLo)
                ldm_x4(a[mt][1], sA + ASZ + (wm * 32 + mt * 16 + arowL) * SROW + acolB);
        }

#pragma unroll
        for (int p = 0; p < 4; p++) {
            uint32_t bh[4];
            ldm_x4(bh, sB + (wn * 64 + p * 16 + arowL) * SROW + acolB);
#pragma unroll
            for (int mt = 0; mt < 2; mt++) {
#pragma unroll
                for (int q = 0; q < 2; q++) {
                    float* dd = d[mt][p * 2 + q];
                    mma_f16(dd, a[mt][0], bh[q], bh[q + 2]);       // Wh * X
                    if (needLo)
                        mma_f16(dd, a[mt][1], bh[q], bh[q + 2]);   // Wl * X
                }
            }
        }
        __syncthreads();
    }

    const int ocW = ocBase + wm * 32;
    if (ocW >= OCH_TOT) return;
    const int y = y0 + wn;
#pragma unroll
    for (int mt = 0; mt < 2; mt++) {
        int r0 = ocW + mt * 16 + (lane >> 2);
        int r1 = r0 + 8;
        float bias0 = (r0 < OCH_OFF) ? __ldg(&b_off[r0]) : __ldg(&b_mod[r0 - OCH_OFF]);
        float bias1 = (r1 < OCH_OFF) ? __ldg(&b_off[r1]) : __ldg(&b_mod[r1 - OCH_OFF]);
        bool c0 = r0 < OCH_OFF, c1 = r1 < OCH_OFF;
        float* base0 = &g_om[(((size_t)b * OCH_TOT + r0) * HH + y) * WW];
        float* base1 = &g_om[(((size_t)b * OCH_TOT + r1) * HH + y) * WW];
#pragma unroll
        for (int nt = 0; nt < 8; nt++) {
            int col = nt * 8 + (lane & 3) * 2;
            float2 v0, v1;
            v0.x = d[mt][nt][0] + bias0; v0.y = d[mt][nt][1] + bias0;
            v1.x = d[mt][nt][2] + bias1; v1.y = d[mt][nt][3] + bias1;
            if (c0) {
                v0.x = fminf(fmaxf(v0.x, -MAXOFF), MAXOFF);
                v0.y = fminf(fmaxf(v0.y, -MAXOFF), MAXOFF);
            }
            if (c1) {
                v1.x = fminf(fmaxf(v1.x, -MAXOFF), MAXOFF);
                v1.y = fminf(fmaxf(v1.y, -MAXOFF), MAXOFF);
            }
            __stcs((float2*)(base0 + col), v0);
            __stcs((float2*)(base1 + col), v1);
        }
    }
}

// ======================= Deform + final GEMM (FFMA2, padded sampling) =====
// CTA = one (b, y) row: 64 px x 128 oc. 256 threads; channel chunks of 4.
// om loads use __ldcs (streaming) so g_xpad stays L2-resident for the gathers.
__global__ __launch_bounds__(256) void deform_gemm_kernel(float* __restrict__ out)
{
    const int y = blockIdx.x;
    const int b = blockIdx.y;
    const int tid = threadIdx.x;
    const int tx = tid & 15;
    const int ty = tid >> 4;
    const int px0 = tx * 4;
    const int oc0 = ty * 8;

    __shared__ __align__(16) float ss[4 * 9 * 64];
    __shared__ __align__(16) float wcs[36][128];

    unsigned long long acc2[4][4];
#pragma unroll
    for (int p = 0; p < 4; p++)
#pragma unroll
        for (int j = 0; j < 4; j++) acc2[p][j] = 0ull;

    const float* xpb = g_xpad + (size_t)b * CIN * (PADW * PADW);
    const float* omb = g_om + (size_t)b * OCH_TOT * (HH * WW);

    for (int c0 = 0; c0 < CIN; c0 += 4) {
        for (int idx = tid; idx < 36 * 128; idx += 256) {
            ((float*)wcs)[idx] = g_wt[(c0 * 9 + (idx >> 7)) * 128 + (idx & 127)];
        }
        for (int s = tid; s < 4 * 9 * 64; s += 256) {
            int px = s & 63;
            int k  = (s >> 6) % 9;
            int cc = s / 576;
            int c  = c0 + cc;
            int ki = k / 3, kj = k % 3;
            float dy = __ldcs(omb + (size_t)(c * 18 + 2 * k) * 4096 + y * WW + px);
            float dx = __ldcs(omb + (size_t)(c * 18 + 2 * k + 1) * 4096 + y * WW + px);
            float m  = __ldcs(omb + (size_t)(OCH_OFF + c * 9 + k) * 4096 + y * WW + px);
            // padded-plane coords (always in [0, 97])
            float py  = dy + (float)(y + ki + 16);
            float pxf = dx + (float)(px + kj + 16);
            int iy = (int)py, ix = (int)pxf;
            float wy = py - (float)iy, wx = pxf - (float)ix;
            const float* p = xpb + (size_t)c * (PADW * PADW) + iy * PADW + ix;
            float v00 = __ldg(p), v01 = __ldg(p + 1);
            float v10 = __ldg(p + PADW), v11 = __ldg(p + PADW + 1);
            float t0 = v00 + wx * (v01 - v00);
            float t1 = v10 + wx * (v11 - v10);
            ss[s] = (t0 + wy * (t1 - t0)) * m;
        }
        __syncthreads();

#pragma unroll
        for (int ck = 0; ck < 36; ck++) {
            float4 sv4 = *(const float4*)&ss[ck * 64 + px0];
            unsigned long long sp[4];
            sp[0] = pack2(sv4.x, sv4.x);
            sp[1] = pack2(sv4.y, sv4.y);
            sp[2] = pack2(sv4.z, sv4.z);
            sp[3] = pack2(sv4.w, sv4.w);
            ulonglong2 w0 = *(const ulonglong2*)&wcs[ck][oc0];
            ulonglong2 w1 = *(const ulonglong2*)&wcs[ck][oc0 + 4];
#pragma unroll
            for (int j = 0; j < 4; j++) {
                acc2[0][j] = ffma2(w0.x, sp[j], acc2[0][j]);
                acc2[1][j] = ffma2(w0.y, sp[j], acc2[1][j]);
                acc2[2][j] = ffma2(w1.x, sp[j], acc2[2][j]);
                acc2[3][j] = ffma2(w1.y, sp[j], acc2[3][j]);
            }
        }
        __syncthreads();
    }

#pragma unroll
    for (int p = 0; p < 4; p++) {
        float lo[4], hi[4];
#pragma unroll
        for (int j = 0; j < 4; j++) unpack2(acc2[p][j], lo[j], hi[j]);
        float4 vlo = make_float4(lo[0], lo[1], lo[2], lo[3]);
        float4 vhi = make_float4(hi[0], hi[1], hi[2], hi[3]);
        int oc = oc0 + 2 * p;
        *(float4*)&out[(((size_t)b * OC_FIN + oc) * HH + y) * WW + px0] = vlo;
        *(float4*)&out[(((size_t)b * OC_FIN + oc + 1) * HH + y) * WW + px0] = vhi;
    }
}

// ---------------------------------------------------------------------------
extern "C" void kernel_launch(void* const* d_in, const int* in_sizes, int n_in,
                              void* d_out, int out_size)
{
    const float* x      = (const float*)d_in[0];
    const float* w_off  = (const float*)d_in[1];
    const float* b_off  = (const float*)d_in[2];
    const float* w_mod  = (const float*)d_in[3];
    const float* b_mod  = (const float*)d_in[4];
    const float* w_conv = (const float*)d_in[5];
    float* out = (float*)d_out;

    // grid must cover the LARGEST prep range (TOT_XTH = 6,488,064)
    prep_all<<<(TOT_XTH + 255) / 256, 256>>>(x, w_off, w_mod, w_conv);
    conv_mma_kernel<<<dim3(14, 32, 8), 256>>>(b_off, b_mod);
    deform_gemm_kernel<<<dim3(HH, BB), 256>>>(out);
}

// round 17
// speedup vs baseline: 1.1014x; 1.0719x over previous
#include <cuda_runtime.h>
#include <cuda_bf16.h>
#include <cuda_fp16.h>
#include <cstdint>

// Problem constants
#define BB   8
#define CIN  64
#define HH   64
#define WW   64
#define OCH_OFF 1152
#define OCH_TOT 1728
#define OCP     1792          // padded oc (14 * 128)
#define OC_FIN  128
#define MAXOFF  16.0f
#define PADW 100              // padded plane 100x100, border 17

// Scratch
__device__ float g_om[(size_t)BB * OCH_TOT * HH * WW];   // conv out [b][r][y][x]
__device__ float g_wt[576 * 128];                        // w_conv transposed [ck][oc]
// zero-padded x: [b][c][100][100], (yy,xx) = (y+17, x+17)
__device__ float g_xpad[(size_t)BB * CIN * PADW * PADW];
// shifted x, fp16: g_xth[kj][b][yy 0..65][cc 0..3][px 0..63][cic 0..15]
__device__ __half g_xth[3 * 8 * 66 * 4 * 64 * 16];
// conv weights fp16 split: g_wh[t][cc][ocp][cic] (zeros oc>=1728)
__device__ __half g_wh_hi[9 * 4 * OCP * 16];
__device__ __half g_wh_lo[9 * 4 * OCP * 16];

// ======================= helpers =======================
__device__ __forceinline__ uint32_t smem_u32(const void* p) {
    uint32_t a;
    asm("{ .reg .u64 t; cvta.to.shared.u64 t, %1; cvt.u32.u64 %0, t; }"
        : "=r"(a) : "l"(p));
    return a;
}
__device__ __forceinline__ void ldm_x4(uint32_t* r, uint32_t addr) {
    asm volatile("ldmatrix.sync.aligned.m8n8.x4.shared.b16 {%0,%1,%2,%3}, [%4];"
                 : "=r"(r[0]), "=r"(r[1]), "=r"(r[2]), "=r"(r[3]) : "r"(addr));
}
__device__ __forceinline__ void mma_f16(float* d, const uint32_t* a,
                                        uint32_t b0, uint32_t b1) {
    asm volatile(
        "mma.sync.aligned.m16n8k16.row.col.f32.f16.f16.f32 "
        "{%0,%1,%2,%3}, {%4,%5,%6,%7}, {%8,%9}, {%0,%1,%2,%3};"
        : "+f"(d[0]), "+f"(d[1]), "+f"(d[2]), "+f"(d[3])
        : "r"(a[0]), "r"(a[1]), "r"(a[2]), "r"(a[3]), "r"(b0), "r"(b1));
}

// ---------------- packed f32x2 helpers (deform kernel) ----------------
__device__ __forceinline__ unsigned long long ffma2(unsigned long long a,
                                                    unsigned long long b,
                                                    unsigned long long c) {
    unsigned long long d;
    asm("fma.rn.f32x2 %0, %1, %2, %3;" : "=l"(d) : "l"(a), "l"(b), "l"(c));
    return d;
}
__device__ __forceinline__ unsigned long long pack2(float lo, float hi) {
    unsigned long long d;
    asm("mov.b64 %0, {%1, %2};" : "=l"(d) : "f"(lo), "f"(hi));
    return d;
}
__device__ __forceinline__ void unpack2(unsigned long long v, float& lo, float& hi) {
    asm("mov.b64 {%0, %1}, %2;" : "=f"(lo), "=f"(hi) : "l"(v));
}

// ======================= Merged prep kernel =======================
// Index ranges (grid must cover the LARGEST = TOT_XTH):
//   TOT_XTH  = 6,488,064   (3*8*66*4*64*16)  <-- largest
//   TOT_XPAD = 5,120,000   (BB*CIN*PADW*PADW)
//   TOT_WH   = 1,032,192   (9*4*OCP*16)
//   TOT_WT   =    73,728   (OC_FIN*576)
#define TOT_XTH  (3 * 8 * 66 * 4 * 64 * 16)
#define TOT_WH   (9 * 4 * OCP * 16)
#define TOT_XPAD (BB * CIN * PADW * PADW)
#define TOT_WT   (OC_FIN * 576)
__global__ void prep_all(const float* __restrict__ x,
                         const float* __restrict__ w_off,
                         const float* __restrict__ w_mod,
                         const float* __restrict__ w_conv) {
    int i = blockIdx.x * 256 + threadIdx.x;

    if (i < TOT_XPAD) {
        int xx = i % PADW;
        int t1 = i / PADW;
        int yy = t1 % PADW;
        int bc = t1 / PADW;
        int sy = yy - 17, sx = xx - 17;
        float v = 0.f;
        if (sy >= 0 && sy < HH && sx >= 0 && sx < WW)
            v = x[((size_t)bc * HH + sy) * WW + sx];
        g_xpad[i] = v;
    }
    if (i < TOT_XTH) {
        int cic = i & 15;
        int t1 = i >> 4;
        int px = t1 & 63;
        int t2 = t1 >> 6;
        int cc = t2 & 3;
        int t3 = t2 >> 2;
        int yy = t3 % 66;
        int t4 = t3 / 66;
        int b  = t4 & 7;
        int kj = t4 >> 3;
        int c = cc * 16 + cic;
        int sy = yy - 1, sx = px + kj - 1;
        float v = 0.f;
        if (sy >= 0 && sy < HH && sx >= 0 && sx < WW)
            v = x[(((size_t)b * CIN + c) * HH + sy) * WW + sx];
        g_xth[i] = __float2half(v);
    }
    if (i < TOT_WH) {
        int cic = i & 15;
        int t1 = i >> 4;
        int oc = t1 % OCP;
        int tcc = t1 / OCP;
        int cc = tcc & 3;
        int tp = tcc >> 2;
        int c = cc * 16 + cic;
        float v = 0.f;
        if (oc < OCH_OFF)      v = w_off[((size_t)oc * CIN + c) * 9 + tp];
        else if (oc < OCH_TOT) v = w_mod[((size_t)(oc - OCH_OFF) * CIN + c) * 9 + tp];
        __half h = __float2half(v);
        g_wh_hi[i] = h;
        g_wh_lo[i] = __float2half(v - __half2float(h));
    }
    if (i < TOT_WT) {
        int oc = i / 576, ck = i % 576;
        g_wt[ck * 128 + oc] = w_conv[i];
    }
}

// ======================= Conv kernel: fp16 split, mask CTAs 1-MMA =========
// CTA: 128 oc x 128 px (2 image rows of one b). 8 warps: wm = w&3 (oc quad),
// wn = w>>2 (row). Warp tile 32 oc x 64 px. K = 9 taps x 4 chunks of 16.
// Offset CTAs (ocBase < 1152): 2-MMA split (Wh + Wl).
// Mask CTAs (ocBase >= 1152): single Wh MMA (mask tolerates fp16 w rounding).
// g_om stores use __stcs (streaming, evict-first) to preserve L2 for g_xpad.
#define SROW 48
#define ASZ 6144               // 128*48
#define BUFSZ 18432            // A_hi + A_lo + B
__global__ __launch_bounds__(256) void conv_mma_kernel(
    const float* __restrict__ b_off, const float* __restrict__ b_mod)
{
    __shared__ __align__(16) char smem[2 * BUFSZ];   // 36 KB
    const uint32_t sb = smem_u32(smem);
    const int tid = threadIdx.x;
    const int lane = tid & 31;
    const int w = tid >> 5;
    const int wm = w & 3;
    const int wn = w >> 2;
    const int ocBase = blockIdx.x * 128;
    const int y0 = blockIdx.y * 2;
    const int b  = blockIdx.z;
    const bool needLo = (ocBase < OCH_OFF);   // block-uniform

    float d[2][8][4];
#pragma unroll
    for (int mt = 0; mt < 2; mt++)
#pragma unroll
        for (int nt = 0; nt < 8; nt++)
#pragma unroll
            for (int e = 0; e < 4; e++) d[mt][nt][e] = 0.f;

    auto stage = [&](int s, int buf) {
        const int t = s >> 2, cc = s & 3;
        const int ki = t / 3, kj = t - ki * 3;
        char* base = smem + buf * BUFSZ;
#pragma unroll
        for (int ii = 0; ii < 3; ii++) {
            int i = tid + ii * 256;
            if (i < 512) {
                int hh = i >> 8, oc = (i >> 1) & 127, j = i & 1;
                if (hh == 0 || needLo) {
                    const __half* src = (hh ? g_wh_lo : g_wh_hi)
                        + (((size_t)(t * 4 + cc) * OCP + ocBase + oc) << 4) + j * 8;
                    *(uint4*)(base + hh * ASZ + oc * SROW + j * 16) = *(const uint4*)src;
                }
            } else {
                i -= 512;
                int px = (i >> 1) & 127, j = i & 1;
                int yy = y0 + (px >> 6) + ki;
                const __half* src = g_xth
                    + ((size_t)(((kj * 8 + b) * 66 + yy) * 4 + cc) << 10)
                    + ((px & 63) << 4) + j * 8;
                *(uint4*)(base + 2 * ASZ + px * SROW + j * 16) = *(const uint4*)src;
            }
        }
    };

    stage(0, 0);
    __syncthreads();

    const int arowL = (lane & 7) + ((lane >> 3) & 1) * 8;
    const int acolB = ((lane >> 4) & 1) * 16;

    for (int s = 0; s < 36; s++) {
        const int buf = s & 1;
        if (s + 1 < 36) stage(s + 1, 1 - buf);

        const uint32_t sA = sb + buf * BUFSZ;
        const uint32_t sB = sA + 2 * ASZ;

        uint32_t a[2][2][4];
#pragma unroll
        for (int mt = 0; mt < 2; mt++) {
            ldm_x4(a[mt][0], sA + (wm * 32 + mt * 16 + arowL) * SROW + acolB);
            if (needLo)
                ldm_x4(a[mt][1], sA + ASZ + (wm * 32 + mt * 16 + arowL) * SROW + acolB);
        }

#pragma unroll
        for (int p = 0; p < 4; p++) {
            uint32_t bh[4];
            ldm_x4(bh, sB + (wn * 64 + p * 16 + arowL) * SROW + acolB);
#pragma unroll
            for (int mt = 0; mt < 2; mt++) {
#pragma unroll
                for (int q = 0; q < 2; q++) {
                    float* dd = d[mt][p * 2 + q];
                    mma_f16(dd, a[mt][0], bh[q], bh[q + 2]);       // Wh * X
                    if (needLo)
                        mma_f16(dd, a[mt][1], bh[q], bh[q + 2]);   // Wl * X
                }
            }
        }
        __syncthreads();
    }

    const int ocW = ocBase + wm * 32;
    if (ocW >= OCH_TOT) return;
    const int y = y0 + wn;
#pragma unroll
    for (int mt = 0; mt < 2; mt++) {
        int r0 = ocW + mt * 16 + (lane >> 2);
        int r1 = r0 + 8;
        float bias0 = (r0 < OCH_OFF) ? __ldg(&b_off[r0]) : __ldg(&b_mod[r0 - OCH_OFF]);
        float bias1 = (r1 < OCH_OFF) ? __ldg(&b_off[r1]) : __ldg(&b_mod[r1 - OCH_OFF]);
        bool c0 = r0 < OCH_OFF, c1 = r1 < OCH_OFF;
        float* base0 = &g_om[(((size_t)b * OCH_TOT + r0) * HH + y) * WW];
        float* base1 = &g_om[(((size_t)b * OCH_TOT + r1) * HH + y) * WW];
#pragma unroll
        for (int nt = 0; nt < 8; nt++) {
            int col = nt * 8 + (lane & 3) * 2;
            float2 v0, v1;
            v0.x = d[mt][nt][0] + bias0; v0.y = d[mt][nt][1] + bias0;
            v1.x = d[mt][nt][2] + bias1; v1.y = d[mt][nt][3] + bias1;
            if (c0) {
                v0.x = fminf(fmaxf(v0.x, -MAXOFF), MAXOFF);
                v0.y = fminf(fmaxf(v0.y, -MAXOFF), MAXOFF);
            }
            if (c1) {
                v1.x = fminf(fmaxf(v1.x, -MAXOFF), MAXOFF);
                v1.y = fminf(fmaxf(v1.y, -MAXOFF), MAXOFF);
            }
            __stcs((float2*)(base0 + col), v0);
            __stcs((float2*)(base1 + col), v1);
        }
    }
}

// ======================= Deform + final GEMM (FFMA2, unrolled sampler) ====
// CTA = one (b, y) row: 64 px x 128 oc. 256 threads; channel chunks of 4.
// Sampler: fixed (px = tid&63, cc = tid>>6), k unrolled 0..8 so all plane
// offsets / ki / kj / ss indices are compile-time; no div/mod in the loop.
__global__ __launch_bounds__(256) void deform_gemm_kernel(float* __restrict__ out)
{
    const int y = blockIdx.x;
    const int b = blockIdx.y;
    const int tid = threadIdx.x;
    const int tx = tid & 15;
    const int ty = tid >> 4;
    const int px0 = tx * 4;
    const int oc0 = ty * 8;
    const int px = tid & 63;          // sampler pixel
    const int ccs = tid >> 6;         // sampler channel-in-chunk

    __shared__ __align__(16) float ss[4 * 9 * 64];
    __shared__ __align__(16) float wcs[36][128];

    unsigned long long acc2[4][4];
#pragma unroll
    for (int p = 0; p < 4; p++)
#pragma unroll
        for (int j = 0; j < 4; j++) acc2[p][j] = 0ull;

    const float* xpb = g_xpad + (size_t)b * CIN * (PADW * PADW);
    const float* omb = g_om + (size_t)b * OCH_TOT * (HH * WW) + y * WW + px;

    for (int c0 = 0; c0 < CIN; c0 += 4) {
        for (int idx = tid; idx < 36 * 128; idx += 256) {
            ((float*)wcs)[idx] = g_wt[(c0 * 9 + (idx >> 7)) * 128 + (idx & 127)];
        }
        {
            const int c = c0 + ccs;
            const float* omc = omb + (size_t)c * 18 * 4096;       // offset planes
            const float* omm = omb + (size_t)(OCH_OFF + c * 9) * 4096; // mask planes
            const float* xpc = xpb + (size_t)c * (PADW * PADW);
            float* ssc = ss + ccs * 576 + px;
#pragma unroll
            for (int k = 0; k < 9; k++) {
                const int ki = k / 3, kj = k - ki * 3;            // compile-time
                float dy = __ldcs(omc + (2 * k) * 4096);
                float dx = __ldcs(omc + (2 * k + 1) * 4096);
                float m  = __ldcs(omm + k * 4096);
                // padded-plane coords (always in [0, 97])
                float py  = dy + (float)(y + ki + 16);
                float pxf = dx + (float)(px + kj + 16);
                int iy = (int)py, ix = (int)pxf;
                float wy = py - (float)iy, wx = pxf - (float)ix;
                const float* p = xpc + iy * PADW + ix;
                float v00 = __ldg(p), v01 = __ldg(p + 1);
                float v10 = __ldg(p + PADW), v11 = __ldg(p + PADW + 1);
                float t0 = v00 + wx * (v01 - v00);
                float t1 = v10 + wx * (v11 - v10);
                ssc[k * 64] = (t0 + wy * (t1 - t0)) * m;
            }
        }
        __syncthreads();

#pragma unroll
        for (int ck = 0; ck < 36; ck++) {
            float4 sv4 = *(const float4*)&ss[ck * 64 + px0];
            unsigned long long sp[4];
            sp[0] = pack2(sv4.x, sv4.x);
            sp[1] = pack2(sv4.y, sv4.y);
            sp[2] = pack2(sv4.z, sv4.z);
            sp[3] = pack2(sv4.w, sv4.w);
            ulonglong2 w0 = *(const ulonglong2*)&wcs[ck][oc0];
            ulonglong2 w1 = *(const ulonglong2*)&wcs[ck][oc0 + 4];
#pragma unroll
            for (int j = 0; j < 4; j++) {
                acc2[0][j] = ffma2(w0.x, sp[j], acc2[0][j]);
                acc2[1][j] = ffma2(w0.y, sp[j], acc2[1][j]);
                acc2[2][j] = ffma2(w1.x, sp[j], acc2[2][j]);
                acc2[3][j] = ffma2(w1.y, sp[j], acc2[3][j]);
            }
        }
        __syncthreads();
    }

#pragma unroll
    for (int p = 0; p < 4; p++) {
        float lo[4], hi[4];
#pragma unroll
        for (int j = 0; j < 4; j++) unpack2(acc2[p][j], lo[j], hi[j]);
        float4 vlo = make_float4(lo[0], lo[1], lo[2], lo[3]);
        float4 vhi = make_float4(hi[0], hi[1], hi[2], hi[3]);
        int oc = oc0 + 2 * p;
        *(float4*)&out[(((size_t)b * OC_FIN + oc) * HH + y) * WW + px0] = vlo;
        *(float4*)&out[(((size_t)b * OC_FIN + oc + 1) * HH + y) * WW + px0] = vhi;
    }
}

// ---------------------------------------------------------------------------
extern "C" void kernel_launch(void* const* d_in, const int* in_sizes, int n_in,
                              void* d_out, int out_size)
{
    const float* x      = (const float*)d_in[0];
    const float* w_off  = (const float*)d_in[1];
    const float* b_off  = (const float*)d_in[2];
    const float* w_mod  = (const float*)d_in[3];
    const float* b_mod  = (const float*)d_in[4];
    const float* w_conv = (const float*)d_in[5];
    float* out = (float*)d_out;

    // grid must cover the LARGEST prep range (TOT_XTH = 6,488,064)
    prep_all<<<(TOT_XTH + 255) / 256, 256>>>(x, w_off, w_mod, w_conv);
    conv_mma_kernel<<<dim3(14, 32, 8), 256>>>(b_off, b_mod);
    deform_gemm_kernel<<<dim3(HH, BB), 256>>>(out);
}